// round 16
// baseline (speedup 1.0000x reference)
#include <cuda_runtime.h>
#include <cuda_bf16.h>
#include <cstdint>
#include <cstddef>

#define Msz 4096
#define Ksz 4096
#define Nsz 4096
#define TKC 64
#define NCHUNK (Ksz / TKC)   // 64

// Scratch (static device globals: allocation-free at runtime)
__device__ __nv_bfloat16 g_Xb[(size_t)Msz * Ksz];   // x as bf16, [M,K] row-major
__device__ __nv_bfloat16 g_Yt[(size_t)Nsz * Ksz];   // y^T as bf16, [N,K] row-major
__device__ float g_R[Msz];                          // rowsum of x
__device__ float g_C[Nsz];                          // colsum of y

__device__ __forceinline__ uint32_t smem_u32(const void* p) {
    uint32_t a;
    asm("{ .reg .u64 t; cvta.to.shared.u64 t, %1; cvt.u32.u64 %0, t; }" : "=r"(a) : "l"(p));
    return a;
}

#define SWZ(off) ((off) ^ (((off) >> 3) & 0x70))

#define MBARRIER_INIT(addr, cnt) \
    asm volatile("mbarrier.init.shared.b64 [%0], %1;" \
                 :: "r"((uint32_t)(addr)), "r"((uint32_t)(cnt)) : "memory")

// Acquire wait: required before generic (ldmatrix) reads of the stage.
#define MBARRIER_WAIT_PARITY(mbar_smem_addr, phase_parity) do { \
    uint32_t _mbar = (uint32_t)(mbar_smem_addr); \
    uint32_t _parity = (uint32_t)(phase_parity); \
    uint32_t _done; \
    asm volatile( \
        "{\n\t.reg .pred p;\n\t" \
        "mbarrier.try_wait.parity.acquire.cta.shared::cta.b64 p, [%1], %2;\n\t" \
        "selp.b32 %0, 1, 0, p;\n\t}" \
        : "=r"(_done) : "r"(_mbar), "r"(_parity) : "memory"); \
    if (!_done) { \
        asm volatile( \
            "{\n\t.reg .pred P1;\n\t" \
            "WAIT_LOOP_%=:\n\t" \
            "mbarrier.try_wait.parity.acquire.cta.shared::cta.b64 P1, [%0], %1, 0x989680;\n\t" \
            "@P1 bra.uni WAIT_DONE_%=;\n\t" \
            "bra.uni WAIT_LOOP_%=;\n\t" \
            "WAIT_DONE_%=:\n\t}" \
            :: "r"(_mbar), "r"(_parity) : "memory"); \
    } \
} while (0)

// Relaxed wait: ONLY for the producer's empty-wait — all post-wait stage accesses
// are cp.async (async proxy), which orders itself; no acquire needed.
#define MBARRIER_WAIT_PARITY_RELAXED(mbar_smem_addr, phase_parity) do { \
    uint32_t _mbar = (uint32_t)(mbar_smem_addr); \
    uint32_t _parity = (uint32_t)(phase_parity); \
    uint32_t _done; \
    asm volatile( \
        "{\n\t.reg .pred p;\n\t" \
        "mbarrier.try_wait.parity.relaxed.cta.shared::cta.b64 p, [%1], %2, 0x989680;\n\t" \
        "selp.b32 %0, 1, 0, p;\n\t}" \
        : "=r"(_done) : "r"(_mbar), "r"(_parity) : "memory"); \
    if (!_done) { \
        asm volatile( \
            "{\n\t.reg .pred P1;\n\t" \
            "WAIT_LOOP_%=:\n\t" \
            "mbarrier.try_wait.parity.relaxed.cta.shared::cta.b64 P1, [%0], %1, 0x989680;\n\t" \
            "@P1 bra.uni WAIT_DONE_%=;\n\t" \
            "bra.uni WAIT_LOOP_%=;\n\t" \
            "WAIT_DONE_%=:\n\t}" \
            :: "r"(_mbar), "r"(_parity) : "memory"); \
    } \
} while (0)

// ---------------- Prep kernels ----------------
// One block per row of x: fp32 -> bf16 convert + rowsum. First 16 blocks also zero g_C
// (safe: prep_y runs in a later launch in the same stream).
__global__ void prep_x_kernel(const float* __restrict__ x) {
    int m = blockIdx.x;
    if (m < 16) {
        int base = m * 256;
        g_C[base + threadIdx.x] = 0.0f;
    }
    const float4* xr = (const float4*)(x + (size_t)m * Ksz);
    uint2* dst = (uint2*)(g_Xb + (size_t)m * Ksz);
    float sum = 0.0f;
    for (int i = threadIdx.x; i < Ksz / 4; i += 256) {
        float4 v = xr[i];
        sum += (v.x + v.y) + (v.z + v.w);
        __nv_bfloat162 lo = __floats2bfloat162_rn(v.x, v.y);
        __nv_bfloat162 hi = __floats2bfloat162_rn(v.z, v.w);
        uint2 u;
        u.x = *reinterpret_cast<uint32_t*>(&lo);
        u.y = *reinterpret_cast<uint32_t*>(&hi);
        dst[i] = u;
    }
    #pragma unroll
    for (int o = 16; o; o >>= 1) sum += __shfl_xor_sync(0xFFFFFFFFu, sum, o);
    __shared__ float ws[8];
    if ((threadIdx.x & 31) == 0) ws[threadIdx.x >> 5] = sum;
    __syncthreads();
    if (threadIdx.x == 0) {
        float t = 0.0f;
        #pragma unroll
        for (int w = 0; w < 8; w++) t += ws[w];
        g_R[m] = t;
    }
}

// 32x32 tile transpose of y into Yt (bf16) + colsum via atomicAdd (partials exact ints)
__global__ void prep_y_kernel(const float* __restrict__ y) {
    __shared__ float tile[32][33];
    int n0 = blockIdx.x * 32, k0 = blockIdx.y * 32;
    int tx = threadIdx.x, ty = threadIdx.y;  // 32 x 8
    #pragma unroll
    for (int r = 0; r < 4; r++)
        tile[ty + r * 8][tx] = y[(size_t)(k0 + ty + r * 8) * Nsz + n0 + tx];
    __syncthreads();
    #pragma unroll
    for (int r = 0; r < 4; r++) {
        int row = ty + r * 8;
        g_Yt[(size_t)(n0 + row) * Ksz + k0 + tx] = __float2bfloat16(tile[tx][row]);
    }
    if (ty == 0) {
        float s = 0.0f;
        #pragma unroll
        for (int i = 0; i < 32; i++) s += tile[i][tx];
        atomicAdd(&g_C[n0 + tx], s);
    }
}

// ---------------- GEMM kernel (bf16 mma.sync, mbarrier-decoupled 3-stage pipeline) ----------------
// Dynamic SMEM: stage s at s*32K: A [0,16K), B [16K,32K). 3 stages = 96 KB.
// mbarriers: full[s] at 96K + s*8, empty[s] at 96K + 24 + s*8.
#define ABYTES 16384
#define STAGEBYTES (2 * ABYTES)
#define NSTAGE 3
#define MBAR_OFF (NSTAGE * STAGEBYTES)     // 98304
#define SMEM_TOTAL (MBAR_OFF + 64)

// Issue this thread's 8 cp.asyncs for one chunk, then async-arrive on full[s].
__device__ __forceinline__ void produce_chunk(uint32_t stage_base, uint32_t full_mbar,
                                              int tid, int m0, int n0, int k0) {
    uint32_t abuf = stage_base;
    uint32_t bbuf = stage_base + ABYTES;
    const char* xb = (const char*)g_Xb;
    const char* yb = (const char*)g_Yt;
    #pragma unroll
    for (int e = 0; e < 4; e++) {
        int idx = tid + e * 256;
        int row = idx >> 3;      // 0..127
        int grp = idx & 7;       // 16B group (8 bf16) within 128B row
        uint32_t soff = SWZ((uint32_t)(row * 128 + grp * 16));
        size_t ea = ((size_t)(m0 + row) * Ksz + (size_t)(k0 + grp * 8)) * 2;
        asm volatile("cp.async.cg.shared.global [%0], [%1], 16;"
                     :: "r"(abuf + soff), "l"(xb + ea) : "memory");
        size_t eb = ((size_t)(n0 + row) * Ksz + (size_t)(k0 + grp * 8)) * 2;
        asm volatile("cp.async.cg.shared.global [%0], [%1], 16;"
                     :: "r"(bbuf + soff), "l"(yb + eb) : "memory");
    }
    // Arrive (without incrementing expected count) once all the above copies land.
    asm volatile("cp.async.mbarrier.arrive.noinc.shared.b64 [%0];"
                 :: "r"(full_mbar) : "memory");
}

__device__ __forceinline__ void load_frags(uint32_t abase, uint32_t bbase, int ks,
                                           int a_row_lo, int a_kg_off,
                                           int b_row_lo, int b_kg_off,
                                           uint32_t afr[2][4], uint32_t bfr[4][4]) {
    #pragma unroll
    for (int mi = 0; mi < 2; mi++) {
        int row = a_row_lo + mi * 16;
        int kg = ks * 2 + a_kg_off;
        uint32_t addr = abase + SWZ((uint32_t)(row * 128 + kg * 16));
        asm volatile("ldmatrix.sync.aligned.m8n8.x4.shared.b16 {%0,%1,%2,%3}, [%4];"
                     : "=r"(afr[mi][0]), "=r"(afr[mi][1]),
                       "=r"(afr[mi][2]), "=r"(afr[mi][3])
                     : "r"(addr));
    }
    #pragma unroll
    for (int nj4 = 0; nj4 < 4; nj4++) {
        int row = b_row_lo + nj4 * 16;
        int kg = ks * 2 + b_kg_off;
        uint32_t addr = bbase + SWZ((uint32_t)(row * 128 + kg * 16));
        asm volatile("ldmatrix.sync.aligned.m8n8.x4.shared.b16 {%0,%1,%2,%3}, [%4];"
                     : "=r"(bfr[nj4][0]), "=r"(bfr[nj4][1]),
                       "=r"(bfr[nj4][2]), "=r"(bfr[nj4][3])
                     : "r"(addr));
    }
}

#define MMA_BLOCK()                                                           \
    _Pragma("unroll")                                                         \
    for (int mi = 0; mi < 2; mi++) {                                          \
        _Pragma("unroll")                                                     \
        for (int nj = 0; nj < 8; nj++) {                                      \
            uint32_t b0 = bfr[nj >> 1][(nj & 1) * 2 + 0];                     \
            uint32_t b1 = bfr[nj >> 1][(nj & 1) * 2 + 1];                     \
            asm volatile(                                                     \
                "mma.sync.aligned.m16n8k16.row.col.f32.bf16.bf16.f32 "        \
                "{%0,%1,%2,%3}, {%4,%5,%6,%7}, {%8,%9}, {%0,%1,%2,%3};"       \
                : "+f"(acc[mi][nj][0]), "+f"(acc[mi][nj][1]),                 \
                  "+f"(acc[mi][nj][2]), "+f"(acc[mi][nj][3])                  \
                : "r"(afr[mi][0]), "r"(afr[mi][1]),                           \
                  "r"(afr[mi][2]), "r"(afr[mi][3]),                           \
                  "r"(b0), "r"(b1));                                          \
        }                                                                     \
    }

__global__ void __launch_bounds__(256, 2) gemm_kernel(float* __restrict__ out) {
    extern __shared__ char smem[];
    uint32_t sb = smem_u32(smem);
    int tid = threadIdx.x;
    int lane = tid & 31;
    int wid = tid >> 5;
    int m0 = blockIdx.y * 128;
    int n0 = blockIdx.x * 128;
    int wm = (wid >> 1) * 32;   // 4 warps in M
    int wn = (wid & 1) * 64;    // 2 warps in N

    uint32_t full_base = sb + MBAR_OFF;
    uint32_t empty_base = sb + MBAR_OFF + 24;

    // Pipeline mbarriers
    if (tid == 0) {
        #pragma unroll
        for (int s2 = 0; s2 < NSTAGE; s2++) {
            MBARRIER_INIT(full_base + s2 * 8, 256);    // full: all threads' copies
            MBARRIER_INIT(empty_base + s2 * 8, 8);     // empty: one arrive per warp
        }
    }
    __syncthreads();

    float acc[2][8][4];
    #pragma unroll
    for (int i = 0; i < 2; i++)
        #pragma unroll
        for (int j = 0; j < 8; j++)
            #pragma unroll
            for (int q = 0; q < 4; q++) acc[i][j][q] = 0.0f;

    // ldmatrix address components (verified in round 2)
    int a_row_lo = wm + (lane & 15);                  // + mi*16
    int a_kg_off = (lane >> 4);                       // + ks*2
    int b_row_lo = wn + ((lane >> 4) << 3) + (lane & 7);   // + nj4*16
    int b_kg_off = ((lane >> 3) & 1);                      // + ks*2

    // Prologue: produce chunks 0 and 1 (stages fresh, no empty wait)
    produce_chunk(sb + 0 * STAGEBYTES, full_base + 0, tid, m0, n0, 0);
    produce_chunk(sb + 1 * STAGEBYTES, full_base + 8, tid, m0, n0, TKC);

    int s = 0;
    unsigned fpar = 0u, epar = 0u;   // bit s = next wait parity for stage s
    for (int c = 0; c < NCHUNK; c++) {
        // Consume chunk c: wait for its copies (acquire), then compute.
        MBARRIER_WAIT_PARITY(full_base + (uint32_t)s * 8, (fpar >> s) & 1u);
        fpar ^= (1u << s);

        uint32_t abase = sb + (uint32_t)s * STAGEBYTES;
        uint32_t bbase = abase + ABYTES;

        uint32_t afr[2][4], bfr[4][4];
        load_frags(abase, bbase, 0, a_row_lo, a_kg_off, b_row_lo, b_kg_off, afr, bfr);

        // ks = 0..2: MMAs then rotate in next fragments (R12 core)
        #pragma unroll
        for (int ks = 0; ks < 3; ks++) {
            MMA_BLOCK();
            load_frags(abase, bbase, ks + 1, a_row_lo, a_kg_off,
                       b_row_lo, b_kg_off, afr, bfr);
        }

        // EARLY RELEASE: ks=3 fragments are in registers — stage s is no longer
        // read by this warp. Arrive empty NOW (was after the ks=3 MMAs in R15),
        // shortening the producer's critical path by ~one MMA block.
        if (lane == 0)
            asm volatile("mbarrier.arrive.shared.b64 _, [%0];"
                         :: "r"(empty_base + (uint32_t)s * 8) : "memory");

        // Produce chunk c+2 while the ks=3 MMAs are still pending below.
        if (c + 2 < NCHUNK) {
            int sn = (s == 0) ? 2 : s - 1;
            if (c + 2 >= NSTAGE) {
                // Relaxed: post-wait stage accesses are cp.async (async proxy) only.
                MBARRIER_WAIT_PARITY_RELAXED(empty_base + (uint32_t)sn * 8,
                                             (epar >> sn) & 1u);
                epar ^= (1u << sn);
            }
            produce_chunk(sb + (uint32_t)sn * STAGEBYTES,
                          full_base + (uint32_t)sn * 8,
                          tid, m0, n0, (c + 2) * TKC);
        }

        // ks = 3 MMAs (fragments already in registers)
        MMA_BLOCK();

        s = (s + 1 == NSTAGE) ? 0 : s + 1;
    }

    // Epilogue: out = 7.5e-4 * (Z - 160*R[m] + 66*C[n] - 4096*66*160)
    const float sc = 7.5e-4f;
    #pragma unroll
    for (int mi = 0; mi < 2; mi++) {
        int r0 = m0 + wm + mi * 16 + (lane >> 2);
        int r1 = r0 + 8;
        float bias0 = fmaf(-160.0f, g_R[r0], -43253760.0f);
        float bias1 = fmaf(-160.0f, g_R[r1], -43253760.0f);
        #pragma unroll
        for (int nj = 0; nj < 8; nj++) {
            int col = n0 + wn + nj * 8 + 2 * (lane & 3);
            float2 cv = *(const float2*)(g_C + col);
            float2 v0, v1;
            v0.x = (acc[mi][nj][0] + bias0 + 66.0f * cv.x) * sc;
            v0.y = (acc[mi][nj][1] + bias0 + 66.0f * cv.y) * sc;
            v1.x = (acc[mi][nj][2] + bias1 + 66.0f * cv.x) * sc;
            v1.y = (acc[mi][nj][3] + bias1 + 66.0f * cv.y) * sc;
            *(float2*)(out + (size_t)r0 * Nsz + col) = v0;
            *(float2*)(out + (size_t)r1 * Nsz + col) = v1;
        }
    }
}

// ---------------- Launch ----------------
extern "C" void kernel_launch(void* const* d_in, const int* in_sizes, int n_in,
                              void* d_out, int out_size) {
    const float* x = (const float*)d_in[0];   // [M, K] fp32 (int-valued)
    const float* y = (const float*)d_in[1];   // [K, N] fp32 (int-valued)
    float* out = (float*)d_out;               // [M, N] fp32

    cudaFuncSetAttribute(gemm_kernel, cudaFuncAttributeMaxDynamicSharedMemorySize, SMEM_TOTAL);

    prep_x_kernel<<<Msz, 256>>>(x);
    prep_y_kernel<<<dim3(Nsz / 32, Ksz / 32), dim3(32, 8)>>>(y);
    gemm_kernel<<<dim3(Nsz / 128, Msz / 128), 256, SMEM_TOTAL>>>(out);
}

// round 17
// speedup vs baseline: 1.0261x; 1.0261x over previous
#include <cuda_runtime.h>
#include <cuda_bf16.h>
#include <cstdint>
#include <cstddef>

#define Msz 4096
#define Ksz 4096
#define Nsz 4096
#define TKC 64
#define NCHUNK (Ksz / TKC)   // 64

// Scratch (static device globals: allocation-free at runtime)
__device__ __nv_bfloat16 g_Xb[(size_t)Msz * Ksz];   // x as bf16, [M,K] row-major
__device__ __nv_bfloat16 g_Yt[(size_t)Nsz * Ksz];   // y^T as bf16, [N,K] row-major
__device__ float g_R[Msz];                          // rowsum of x
__device__ float g_C[Nsz];                          // colsum of y

__device__ __forceinline__ uint32_t smem_u32(const void* p) {
    uint32_t a;
    asm("{ .reg .u64 t; cvta.to.shared.u64 t, %1; cvt.u32.u64 %0, t; }" : "=r"(a) : "l"(p));
    return a;
}

#define SWZ(off) ((off) ^ (((off) >> 3) & 0x70))

#define MBARRIER_INIT(addr, cnt) \
    asm volatile("mbarrier.init.shared.b64 [%0], %1;" \
                 :: "r"((uint32_t)(addr)), "r"((uint32_t)(cnt)) : "memory")

// Acquire wait: required before generic (ldmatrix) reads of the stage.
#define MBARRIER_WAIT_PARITY(mbar_smem_addr, phase_parity) do { \
    uint32_t _mbar = (uint32_t)(mbar_smem_addr); \
    uint32_t _parity = (uint32_t)(phase_parity); \
    uint32_t _done; \
    asm volatile( \
        "{\n\t.reg .pred p;\n\t" \
        "mbarrier.try_wait.parity.acquire.cta.shared::cta.b64 p, [%1], %2;\n\t" \
        "selp.b32 %0, 1, 0, p;\n\t}" \
        : "=r"(_done) : "r"(_mbar), "r"(_parity) : "memory"); \
    if (!_done) { \
        asm volatile( \
            "{\n\t.reg .pred P1;\n\t" \
            "WAIT_LOOP_%=:\n\t" \
            "mbarrier.try_wait.parity.acquire.cta.shared::cta.b64 P1, [%0], %1, 0x989680;\n\t" \
            "@P1 bra.uni WAIT_DONE_%=;\n\t" \
            "bra.uni WAIT_LOOP_%=;\n\t" \
            "WAIT_DONE_%=:\n\t}" \
            :: "r"(_mbar), "r"(_parity) : "memory"); \
    } \
} while (0)

// ---------------- Prep kernels ----------------
// One block per row of x: fp32 -> bf16 convert + rowsum. First 16 blocks also zero g_C
// (safe: prep_y runs in a later launch in the same stream).
__global__ void prep_x_kernel(const float* __restrict__ x) {
    int m = blockIdx.x;
    if (m < 16) {
        int base = m * 256;
        g_C[base + threadIdx.x] = 0.0f;
    }
    const float4* xr = (const float4*)(x + (size_t)m * Ksz);
    uint2* dst = (uint2*)(g_Xb + (size_t)m * Ksz);
    float sum = 0.0f;
    for (int i = threadIdx.x; i < Ksz / 4; i += 256) {
        float4 v = xr[i];
        sum += (v.x + v.y) + (v.z + v.w);
        __nv_bfloat162 lo = __floats2bfloat162_rn(v.x, v.y);
        __nv_bfloat162 hi = __floats2bfloat162_rn(v.z, v.w);
        uint2 u;
        u.x = *reinterpret_cast<uint32_t*>(&lo);
        u.y = *reinterpret_cast<uint32_t*>(&hi);
        dst[i] = u;
    }
    #pragma unroll
    for (int o = 16; o; o >>= 1) sum += __shfl_xor_sync(0xFFFFFFFFu, sum, o);
    __shared__ float ws[8];
    if ((threadIdx.x & 31) == 0) ws[threadIdx.x >> 5] = sum;
    __syncthreads();
    if (threadIdx.x == 0) {
        float t = 0.0f;
        #pragma unroll
        for (int w = 0; w < 8; w++) t += ws[w];
        g_R[m] = t;
    }
}

// prep_y v2: 64x64 tile transpose of y into Yt (bf16) + colsum.
// 256 threads as (tx 0..31, ty 0..7). Reads: float2-coalesced rows.
// Writes: 64 rows x 128B full lines (bf16x2 per lane). Colsum: 64 threads, 1 atomic each.
__global__ void prep_y_kernel(const float* __restrict__ y) {
    __shared__ float tile[64][65];
    int n0 = blockIdx.x * 64, k0 = blockIdx.y * 64;
    int tx = threadIdx.x & 31;
    int ty = threadIdx.x >> 5;   // 0..7
    // Load 64 rows (k) x 64 cols (n); each (tx,ty) covers 8 rows, 2 cols per row.
    #pragma unroll
    for (int j = 0; j < 8; j++) {
        int kk = ty + j * 8;
        float2 v = *(const float2*)(y + (size_t)(k0 + kk) * Nsz + n0 + 2 * tx);
        tile[kk][2 * tx + 0] = v.x;
        tile[kk][2 * tx + 1] = v.y;
    }
    __syncthreads();
    // Store transposed: row = n (64 rows), cols = k (64 bf16 = 128B per row).
    #pragma unroll
    for (int j = 0; j < 8; j++) {
        int row = ty + j * 8;                 // n-index within tile
        __nv_bfloat162 p = __floats2bfloat162_rn(tile[2 * tx + 0][row],
                                                 tile[2 * tx + 1][row]);
        *(__nv_bfloat162*)(g_Yt + (size_t)(n0 + row) * Ksz + k0 + 2 * tx) = p;
    }
    // Colsum partials: 64 threads each own one n-column, sum 64 k-values.
    if (threadIdx.x < 64) {
        int col = threadIdx.x;
        float s = 0.0f;
        #pragma unroll
        for (int i = 0; i < 64; i++) s += tile[i][col];
        atomicAdd(&g_C[n0 + col], s);
    }
}

// ---------------- GEMM kernel (bf16 mma.sync, mbarrier-decoupled 3-stage pipeline) ----------------
// Dynamic SMEM: stage s at s*32K: A [0,16K), B [16K,32K). 3 stages = 96 KB.
// mbarriers: full[s] at 96K + s*8, empty[s] at 96K + 24 + s*8.
#define ABYTES 16384
#define STAGEBYTES (2 * ABYTES)
#define NSTAGE 3
#define MBAR_OFF (NSTAGE * STAGEBYTES)     // 98304
#define SMEM_TOTAL (MBAR_OFF + 64)

// Issue this thread's 8 cp.asyncs for one chunk, then async-arrive on full[s].
__device__ __forceinline__ void produce_chunk(uint32_t stage_base, uint32_t full_mbar,
                                              int tid, int m0, int n0, int k0) {
    uint32_t abuf = stage_base;
    uint32_t bbuf = stage_base + ABYTES;
    const char* xb = (const char*)g_Xb;
    const char* yb = (const char*)g_Yt;
    #pragma unroll
    for (int e = 0; e < 4; e++) {
        int idx = tid + e * 256;
        int row = idx >> 3;      // 0..127
        int grp = idx & 7;       // 16B group (8 bf16) within 128B row
        uint32_t soff = SWZ((uint32_t)(row * 128 + grp * 16));
        size_t ea = ((size_t)(m0 + row) * Ksz + (size_t)(k0 + grp * 8)) * 2;
        asm volatile("cp.async.cg.shared.global [%0], [%1], 16;"
                     :: "r"(abuf + soff), "l"(xb + ea) : "memory");
        size_t eb = ((size_t)(n0 + row) * Ksz + (size_t)(k0 + grp * 8)) * 2;
        asm volatile("cp.async.cg.shared.global [%0], [%1], 16;"
                     :: "r"(bbuf + soff), "l"(yb + eb) : "memory");
    }
    // Arrive (without incrementing expected count) once all the above copies land.
    asm volatile("cp.async.mbarrier.arrive.noinc.shared.b64 [%0];"
                 :: "r"(full_mbar) : "memory");
}

__device__ __forceinline__ void load_frags(uint32_t abase, uint32_t bbase, int ks,
                                           int a_row_lo, int a_kg_off,
                                           int b_row_lo, int b_kg_off,
                                           uint32_t afr[2][4], uint32_t bfr[4][4]) {
    #pragma unroll
    for (int mi = 0; mi < 2; mi++) {
        int row = a_row_lo + mi * 16;
        int kg = ks * 2 + a_kg_off;
        uint32_t addr = abase + SWZ((uint32_t)(row * 128 + kg * 16));
        asm volatile("ldmatrix.sync.aligned.m8n8.x4.shared.b16 {%0,%1,%2,%3}, [%4];"
                     : "=r"(afr[mi][0]), "=r"(afr[mi][1]),
                       "=r"(afr[mi][2]), "=r"(afr[mi][3])
                     : "r"(addr));
    }
    #pragma unroll
    for (int nj4 = 0; nj4 < 4; nj4++) {
        int row = b_row_lo + nj4 * 16;
        int kg = ks * 2 + b_kg_off;
        uint32_t addr = bbase + SWZ((uint32_t)(row * 128 + kg * 16));
        asm volatile("ldmatrix.sync.aligned.m8n8.x4.shared.b16 {%0,%1,%2,%3}, [%4];"
                     : "=r"(bfr[nj4][0]), "=r"(bfr[nj4][1]),
                       "=r"(bfr[nj4][2]), "=r"(bfr[nj4][3])
                     : "r"(addr));
    }
}

#define MMA_BLOCK()                                                           \
    _Pragma("unroll")                                                         \
    for (int mi = 0; mi < 2; mi++) {                                          \
        _Pragma("unroll")                                                     \
        for (int nj = 0; nj < 8; nj++) {                                      \
            uint32_t b0 = bfr[nj >> 1][(nj & 1) * 2 + 0];                     \
            uint32_t b1 = bfr[nj >> 1][(nj & 1) * 2 + 1];                     \
            asm volatile(                                                     \
                "mma.sync.aligned.m16n8k16.row.col.f32.bf16.bf16.f32 "        \
                "{%0,%1,%2,%3}, {%4,%5,%6,%7}, {%8,%9}, {%0,%1,%2,%3};"       \
                : "+f"(acc[mi][nj][0]), "+f"(acc[mi][nj][1]),                 \
                  "+f"(acc[mi][nj][2]), "+f"(acc[mi][nj][3])                  \
                : "r"(afr[mi][0]), "r"(afr[mi][1]),                           \
                  "r"(afr[mi][2]), "r"(afr[mi][3]),                           \
                  "r"(b0), "r"(b1));                                          \
        }                                                                     \
    }

__global__ void __launch_bounds__(256, 2) gemm_kernel(float* __restrict__ out) {
    extern __shared__ char smem[];
    uint32_t sb = smem_u32(smem);
    int tid = threadIdx.x;
    int lane = tid & 31;
    int wid = tid >> 5;
    int m0 = blockIdx.y * 128;
    int n0 = blockIdx.x * 128;
    int wm = (wid >> 1) * 32;   // 4 warps in M
    int wn = (wid & 1) * 64;    // 2 warps in N

    uint32_t full_base = sb + MBAR_OFF;
    uint32_t empty_base = sb + MBAR_OFF + 24;

    // Pipeline mbarriers
    if (tid == 0) {
        #pragma unroll
        for (int s2 = 0; s2 < NSTAGE; s2++) {
            MBARRIER_INIT(full_base + s2 * 8, 256);    // full: all threads' copies
            MBARRIER_INIT(empty_base + s2 * 8, 8);     // empty: one arrive per warp
        }
    }
    __syncthreads();

    float acc[2][8][4];
    #pragma unroll
    for (int i = 0; i < 2; i++)
        #pragma unroll
        for (int j = 0; j < 8; j++)
            #pragma unroll
            for (int q = 0; q < 4; q++) acc[i][j][q] = 0.0f;

    // ldmatrix address components (verified in round 2)
    int a_row_lo = wm + (lane & 15);                  // + mi*16
    int a_kg_off = (lane >> 4);                       // + ks*2
    int b_row_lo = wn + ((lane >> 4) << 3) + (lane & 7);   // + nj4*16
    int b_kg_off = ((lane >> 3) & 1);                      // + ks*2

    // Prologue: produce chunks 0 and 1 (stages fresh, no empty wait)
    produce_chunk(sb + 0 * STAGEBYTES, full_base + 0, tid, m0, n0, 0);
    produce_chunk(sb + 1 * STAGEBYTES, full_base + 8, tid, m0, n0, TKC);

    int s = 0;
    unsigned fpar = 0u, epar = 0u;   // bit s = next wait parity for stage s
    for (int c = 0; c < NCHUNK; c++) {
        // Consume chunk c: wait for its copies (acquire), then compute.
        MBARRIER_WAIT_PARITY(full_base + (uint32_t)s * 8, (fpar >> s) & 1u);
        fpar ^= (1u << s);

        uint32_t abase = sb + (uint32_t)s * STAGEBYTES;
        uint32_t bbase = abase + ABYTES;

        uint32_t afr[2][4], bfr[4][4];
        load_frags(abase, bbase, 0, a_row_lo, a_kg_off, b_row_lo, b_kg_off, afr, bfr);

        // ks = 0..2: MMAs then rotate in next fragments (R12 core)
        #pragma unroll
        for (int ks = 0; ks < 3; ks++) {
            MMA_BLOCK();
            load_frags(abase, bbase, ks + 1, a_row_lo, a_kg_off,
                       b_row_lo, b_kg_off, afr, bfr);
        }

        // Produce chunk c+2 while the ks=3 MMAs are still pending below.
        if (c + 2 < NCHUNK) {
            int sn = (s == 0) ? 2 : s - 1;
            if (c + 2 >= NSTAGE) {
                MBARRIER_WAIT_PARITY(empty_base + (uint32_t)sn * 8,
                                     (epar >> sn) & 1u);
                epar ^= (1u << sn);
            }
            produce_chunk(sb + (uint32_t)sn * STAGEBYTES,
                          full_base + (uint32_t)sn * 8,
                          tid, m0, n0, (c + 2) * TKC);
        }

        // ks = 3 MMAs (fragments already in registers)
        MMA_BLOCK();

        // This warp is done reading stage s.
        if (lane == 0)
            asm volatile("mbarrier.arrive.shared.b64 _, [%0];"
                         :: "r"(empty_base + (uint32_t)s * 8) : "memory");

        s = (s + 1 == NSTAGE) ? 0 : s + 1;
    }

    // Epilogue: out = 7.5e-4 * (Z - 160*R[m] + 66*C[n] - 4096*66*160)
    const float sc = 7.5e-4f;
    #pragma unroll
    for (int mi = 0; mi < 2; mi++) {
        int r0 = m0 + wm + mi * 16 + (lane >> 2);
        int r1 = r0 + 8;
        float bias0 = fmaf(-160.0f, g_R[r0], -43253760.0f);
        float bias1 = fmaf(-160.0f, g_R[r1], -43253760.0f);
        #pragma unroll
        for (int nj = 0; nj < 8; nj++) {
            int col = n0 + wn + nj * 8 + 2 * (lane & 3);
            float2 cv = *(const float2*)(g_C + col);
            float2 v0, v1;
            v0.x = (acc[mi][nj][0] + bias0 + 66.0f * cv.x) * sc;
            v0.y = (acc[mi][nj][1] + bias0 + 66.0f * cv.y) * sc;
            v1.x = (acc[mi][nj][2] + bias1 + 66.0f * cv.x) * sc;
            v1.y = (acc[mi][nj][3] + bias1 + 66.0f * cv.y) * sc;
            *(float2*)(out + (size_t)r0 * Nsz + col) = v0;
            *(float2*)(out + (size_t)r1 * Nsz + col) = v1;
        }
    }
}

// ---------------- Launch ----------------
extern "C" void kernel_launch(void* const* d_in, const int* in_sizes, int n_in,
                              void* d_out, int out_size) {
    const float* x = (const float*)d_in[0];   // [M, K] fp32 (int-valued)
    const float* y = (const float*)d_in[1];   // [K, N] fp32 (int-valued)
    float* out = (float*)d_out;               // [M, N] fp32

    cudaFuncSetAttribute(gemm_kernel, cudaFuncAttributeMaxDynamicSharedMemorySize, SMEM_TOTAL);

    prep_x_kernel<<<Msz, 256>>>(x);
    prep_y_kernel<<<dim3(Nsz / 64, Ksz / 64), 256>>>(y);
    gemm_kernel<<<dim3(Nsz / 128, Msz / 128), 256, SMEM_TOTAL>>>(out);
}